// round 2
// baseline (speedup 1.0000x reference)
#include <cuda_runtime.h>
#include <cstdint>

#define VOCAB_MAX 100000
#define D 64
#define K 32

// Scratch (alloc-free rule: __device__ globals)
__device__ float g_P[(size_t)VOCAB_MAX * D];   // u2e @ W1a
__device__ float g_Q[(size_t)VOCAB_MAX * D];   // u2e @ W1b + b1
__device__ unsigned int g_mask[2097152];       // normalized 32-bit mask per node (N up to 2M)
__device__ int g_flags[2];                     // [0]=nonbin_int, [1]=nonbin_float

// ---------------- packed f32x2 helpers ----------------
__device__ __forceinline__ unsigned long long pack2(float lo, float hi) {
    unsigned long long r;
    asm("mov.b64 %0, {%1, %2};" : "=l"(r) : "f"(lo), "f"(hi));
    return r;
}
__device__ __forceinline__ void unpack2(unsigned long long v, float& lo, float& hi) {
    asm("mov.b64 {%0, %1}, %2;" : "=f"(lo), "=f"(hi) : "l"(v));
}
__device__ __forceinline__ unsigned long long fma2(unsigned long long a,
                                                   unsigned long long b,
                                                   unsigned long long c) {
    unsigned long long d;
    asm("fma.rn.f32x2 %0, %1, %2, %3;" : "=l"(d) : "l"(a), "l"(b), "l"(c));
    return d;
}

// ---------------- mask dtype detection + normalization ----------------
__global__ void mask_init_kernel() { g_flags[0] = 0; g_flags[1] = 0; }

// Scan n_words 32-bit words (n_words = N*K/4, safe under byte/int/float interpretations).
__global__ void mask_detect_kernel(const unsigned int* __restrict__ buf, int n_words) {
    int nonbin_int = 0, nonbin_float = 0;
    for (int i = blockIdx.x * blockDim.x + threadIdx.x; i < n_words;
         i += gridDim.x * blockDim.x) {
        unsigned int w = buf[i];
        if (w != 0u && w != 1u) nonbin_int = 1;
        if (w != 0u && w != 0x3f800000u) nonbin_float = 1;
    }
    if (nonbin_int)   atomicOr(&g_flags[0], 1);
    if (nonbin_float) atomicOr(&g_flags[1], 1);
}

// One thread per node: build 32-bit mask from whichever dtype the buffer holds.
__global__ void mask_convert_kernel(const void* __restrict__ buf, int n_nodes) {
    int n = blockIdx.x * blockDim.x + threadIdx.x;
    if (n >= n_nodes) return;
    int nonbin_int = g_flags[0], nonbin_float = g_flags[1];
    // mode: 0 = float32, 1 = int32, 2 = bool bytes
    int mode = (!nonbin_float) ? 0 : ((!nonbin_int) ? 1 : 2);
    unsigned int m = 0;
    if (mode == 0) {
        const float* p = (const float*)buf + (size_t)n * K;
        for (int k = 0; k < K; k++) if (p[k] != 0.f) m |= (1u << k);
    } else if (mode == 1) {
        const int* p = (const int*)buf + (size_t)n * K;
        for (int k = 0; k < K; k++) if (p[k] != 0) m |= (1u << k);
    } else {
        const unsigned char* p = (const unsigned char*)buf + (size_t)n * K;
        for (int k = 0; k < K; k++) if (p[k] != 0) m |= (1u << k);
    }
    g_mask[n] = m;
}

// ---------------- precompute P = u2e@W1a, Q = u2e@W1b + b1 ----------------
// W1 is [2D, D] row-major: rows [0,64) multiply e_u (W1a), rows [64,128) multiply u_rep (W1b).
__global__ __launch_bounds__(256) void prep_kernel(const float* __restrict__ u2e,
                                                   const float* __restrict__ W1,
                                                   const float* __restrict__ b1,
                                                   int V) {
    __shared__ ulonglong2 sW1[128 * 16];   // 32KB
    {
        const float4* W1v = (const float4*)W1;
        float4* sv = (float4*)sW1;
        for (int i = threadIdx.x; i < 128 * 16; i += 256) sv[i] = W1v[i];
    }
    __syncthreads();

    int v = blockIdx.x * blockDim.x + threadIdx.x;
    if (v >= V) return;

    float r[D];
    const float4* row = (const float4*)(u2e + (size_t)v * D);
#pragma unroll
    for (int i = 0; i < 16; i++) {
        float4 t = row[i];
        r[4 * i + 0] = t.x; r[4 * i + 1] = t.y; r[4 * i + 2] = t.z; r[4 * i + 3] = t.w;
    }

    unsigned long long acc[32];
#pragma unroll
    for (int j = 0; j < 32; j++) acc[j] = 0ull;
#pragma unroll
    for (int i = 0; i < 64; i++) {
        unsigned long long a2 = pack2(r[i], r[i]);
        const ulonglong2* wr = sW1 + i * 16;
#pragma unroll
        for (int jj = 0; jj < 16; jj++) {
            ulonglong2 w = wr[jj];
            acc[2 * jj]     = fma2(a2, w.x, acc[2 * jj]);
            acc[2 * jj + 1] = fma2(a2, w.y, acc[2 * jj + 1]);
        }
    }
    {
        float4* Pr = (float4*)(g_P + (size_t)v * D);
#pragma unroll
        for (int jj = 0; jj < 16; jj++) {
            float a, b, c, d2;
            unpack2(acc[2 * jj], a, b);
            unpack2(acc[2 * jj + 1], c, d2);
            Pr[jj] = make_float4(a, b, c, d2);
        }
    }

#pragma unroll
    for (int j = 0; j < 32; j++) acc[j] = pack2(b1[2 * j], b1[2 * j + 1]);
#pragma unroll
    for (int i = 0; i < 64; i++) {
        unsigned long long a2 = pack2(r[i], r[i]);
        const ulonglong2* wr = sW1 + (64 + i) * 16;
#pragma unroll
        for (int jj = 0; jj < 16; jj++) {
            ulonglong2 w = wr[jj];
            acc[2 * jj]     = fma2(a2, w.x, acc[2 * jj]);
            acc[2 * jj + 1] = fma2(a2, w.y, acc[2 * jj + 1]);
        }
    }
    {
        float4* Qr = (float4*)(g_Q + (size_t)v * D);
#pragma unroll
        for (int jj = 0; jj < 16; jj++) {
            float a, b, c, d2;
            unpack2(acc[2 * jj], a, b);
            unpack2(acc[2 * jj + 1], c, d2);
            Qr[jj] = make_float4(a, b, c, d2);
        }
    }
}

// ---------------- reduce-scatter stage (warp-wide column sums) ----------------
template <int OFF, int HALF>
__device__ __forceinline__ void rs_stage(float* part, int lane) {
    bool up = (lane & OFF) != 0;
#pragma unroll
    for (int j = 0; j < HALF; j++) {
        float send  = up ? part[j] : part[j + HALF];
        float other = __shfl_xor_sync(0xffffffffu, send, OFF);
        float keep  = up ? part[j + HALF] : part[j];
        part[j] = keep + other;
    }
}

// ---------------- main fused kernel: one warp per node, one lane per neighbor ----------------
__global__ __launch_bounds__(128, 3) void agg_kernel(
    const float* __restrict__ u2e,
    const float* __restrict__ W2, const float* __restrict__ b2,
    const float* __restrict__ W3, const float* __restrict__ b3,
    const int* __restrict__ nodes, const int* __restrict__ neigh_idx,
    float* __restrict__ out, int n_nodes) {
    __shared__ ulonglong2 sW2[64 * 16];   // 16KB: W2 [64,64] as f32x2 pairs
    __shared__ float sW3[64];
    __shared__ float sb2[64];
    {
        const float4* W2v = (const float4*)W2;
        float4* sv = (float4*)sW2;
        for (int i = threadIdx.x; i < 1024; i += 128) sv[i] = W2v[i];
        if (threadIdx.x < 64) { sW3[threadIdx.x] = W3[threadIdx.x]; sb2[threadIdx.x] = b2[threadIdx.x]; }
    }
    __syncthreads();

    int warp = threadIdx.x >> 5, lane = threadIdx.x & 31;
    int n = blockIdx.x * 4 + warp;
    if (n >= n_nodes) return;

    int node = nodes[n];                       // uniform per warp
    int idx  = neigh_idx[n * K + lane];        // this lane's neighbor
    unsigned int m = (g_mask[n] >> lane) & 1u;

    // ---- layer 1: h1 = relu(P[idx] + Q[node])  (Q already contains b1) ----
    float h1[D];
    {
        const float4* Pr = (const float4*)(g_P + (size_t)idx * D);
        const float4* Qr = (const float4*)(g_Q + (size_t)node * D);
#pragma unroll
        for (int i = 0; i < 16; i++) {
            float4 p = Pr[i];
            float4 q = Qr[i];
            h1[4 * i + 0] = fmaxf(p.x + q.x, 0.f);
            h1[4 * i + 1] = fmaxf(p.y + q.y, 0.f);
            h1[4 * i + 2] = fmaxf(p.z + q.z, 0.f);
            h1[4 * i + 3] = fmaxf(p.w + q.w, 0.f);
        }
    }

    // ---- layer 2: h2 = h1 @ W2 + b2 (packed f32x2 FMA, W2 broadcast from SMEM) ----
    unsigned long long acc[32];
#pragma unroll
    for (int j = 0; j < 32; j++) acc[j] = pack2(sb2[2 * j], sb2[2 * j + 1]);
#pragma unroll
    for (int i = 0; i < 64; i++) {
        unsigned long long a2 = pack2(h1[i], h1[i]);
        const ulonglong2* wr = sW2 + i * 16;
#pragma unroll
        for (int jj = 0; jj < 16; jj++) {
            ulonglong2 w = wr[jj];
            acc[2 * jj]     = fma2(a2, w.x, acc[2 * jj]);
            acc[2 * jj + 1] = fma2(a2, w.y, acc[2 * jj + 1]);
        }
    }

    // ---- layer 3: score = relu(h2) . W3 + b3 ----
    float score = b3[0];
#pragma unroll
    for (int j = 0; j < 32; j++) {
        float lo, hi;
        unpack2(acc[j], lo, hi);
        score = fmaf(fmaxf(lo, 0.f), sW3[2 * j], score);
        score = fmaf(fmaxf(hi, 0.f), sW3[2 * j + 1], score);
    }

    // ---- masked softmax across the warp (K = 32 = warp width) ----
    float s = m ? score : -1e30f;
    float mx = s;
#pragma unroll
    for (int o = 16; o; o >>= 1) mx = fmaxf(mx, __shfl_xor_sync(0xffffffffu, mx, o));
    float e = __expf(s - mx);                  // masked lanes underflow to exactly 0
    float sum = e;
#pragma unroll
    for (int o = 16; o; o >>= 1) sum += __shfl_xor_sync(0xffffffffu, sum, o);
    float att = __fdividef(e, sum);

    // ---- out[n] = sum_k att_k * u2e[idx_k] : reduce-scatter over the warp ----
    float part[D];
    {
        const float4* Er = (const float4*)(u2e + (size_t)idx * D);
#pragma unroll
        for (int i = 0; i < 16; i++) {
            float4 v = Er[i];
            part[4 * i + 0] = v.x * att;
            part[4 * i + 1] = v.y * att;
            part[4 * i + 2] = v.z * att;
            part[4 * i + 3] = v.w * att;
        }
    }
    rs_stage<16, 32>(part, lane);
    rs_stage<8, 16>(part, lane);
    rs_stage<4, 8>(part, lane);
    rs_stage<2, 4>(part, lane);
    rs_stage<1, 2>(part, lane);
    // lane owns out[n][2*lane], out[n][2*lane+1]
    ((float2*)out)[n * 32 + lane] = make_float2(part[0], part[1]);
}

// ---------------- launch ----------------
// Input order (metadata): u2e, W1, b1, W2, b2, W3, b3, nodes, neigh_idx, neigh_mask
extern "C" void kernel_launch(void* const* d_in, const int* in_sizes, int n_in,
                              void* d_out, int out_size) {
    const float* u2e = (const float*)d_in[0];
    const float* W1  = (const float*)d_in[1];
    const float* b1  = (const float*)d_in[2];
    const float* W2  = (const float*)d_in[3];
    const float* b2  = (const float*)d_in[4];
    const float* W3  = (const float*)d_in[5];
    const float* b3  = (const float*)d_in[6];
    const int*   nodes     = (const int*)d_in[7];
    const int*   neigh_idx = (const int*)d_in[8];
    const void*  neigh_mask = d_in[9];
    float* out = (float*)d_out;

    int V = in_sizes[0] / D;
    if (V > VOCAB_MAX) V = VOCAB_MAX;
    int n_nodes = in_sizes[7];
    int mask_elems = in_sizes[9];              // N*K elements (dtype unknown)
    int n_words = mask_elems / 4;              // safe word count under all dtypes

    mask_init_kernel<<<1, 1>>>();
    mask_detect_kernel<<<256, 256>>>((const unsigned int*)neigh_mask, n_words);
    mask_convert_kernel<<<(n_nodes + 255) / 256, 256>>>(neigh_mask, n_nodes);
    prep_kernel<<<(V + 255) / 256, 256>>>(u2e, W1, b1, V);
    agg_kernel<<<(n_nodes + 3) / 4, 128>>>(u2e, W2, b2, W3, b3,
                                           nodes, neigh_idx, out, n_nodes);
}

// round 3
// speedup vs baseline: 1.0090x; 1.0090x over previous
#include <cuda_runtime.h>
#include <cstdint>

#define VOCAB_MAX 100000
#define D 64
#define K 32

// Scratch (alloc-free rule: __device__ globals)
__device__ float g_P[(size_t)VOCAB_MAX * D];   // u2e @ W1a
__device__ float g_Q[(size_t)VOCAB_MAX * D];   // u2e @ W1b + b1
__device__ unsigned int g_mask[2097152];       // normalized 32-bit mask per node
__device__ int g_flags[2];                     // [0]=nonbin_int, [1]=nonbin_float

// ---------------- packed f32x2 helpers ----------------
__device__ __forceinline__ unsigned long long pack2(float lo, float hi) {
    unsigned long long r;
    asm("mov.b64 %0, {%1, %2};" : "=l"(r) : "f"(lo), "f"(hi));
    return r;
}
__device__ __forceinline__ void unpack2(unsigned long long v, float& lo, float& hi) {
    asm("mov.b64 {%0, %1}, %2;" : "=f"(lo), "=f"(hi) : "l"(v));
}
__device__ __forceinline__ unsigned long long fma2(unsigned long long a,
                                                   unsigned long long b,
                                                   unsigned long long c) {
    unsigned long long d;
    asm("fma.rn.f32x2 %0, %1, %2, %3;" : "=l"(d) : "l"(a), "l"(b), "l"(c));
    return d;
}

// ---------------- mask dtype detection + normalization ----------------
__global__ void mask_init_kernel() { g_flags[0] = 0; g_flags[1] = 0; }

__global__ void mask_detect_kernel(const unsigned int* __restrict__ buf, int n_words) {
    int nonbin_int = 0, nonbin_float = 0;
    for (int i = blockIdx.x * blockDim.x + threadIdx.x; i < n_words;
         i += gridDim.x * blockDim.x) {
        unsigned int w = buf[i];
        if (w != 0u && w != 1u) nonbin_int = 1;
        if (w != 0u && w != 0x3f800000u) nonbin_float = 1;
    }
    if (nonbin_int)   atomicOr(&g_flags[0], 1);
    if (nonbin_float) atomicOr(&g_flags[1], 1);
}

__global__ void mask_convert_kernel(const void* __restrict__ buf, int n_nodes) {
    int n = blockIdx.x * blockDim.x + threadIdx.x;
    if (n >= n_nodes) return;
    int nonbin_int = g_flags[0], nonbin_float = g_flags[1];
    int mode = (!nonbin_float) ? 0 : ((!nonbin_int) ? 1 : 2);  // 0=f32, 1=i32, 2=bytes
    unsigned int m = 0;
    if (mode == 0) {
        const float* p = (const float*)buf + (size_t)n * K;
        for (int k = 0; k < K; k++) if (p[k] != 0.f) m |= (1u << k);
    } else if (mode == 1) {
        const int* p = (const int*)buf + (size_t)n * K;
        for (int k = 0; k < K; k++) if (p[k] != 0) m |= (1u << k);
    } else {
        const unsigned char* p = (const unsigned char*)buf + (size_t)n * K;
        for (int k = 0; k < K; k++) if (p[k] != 0) m |= (1u << k);
    }
    g_mask[n] = m;
}

// ---------------- precompute P = u2e@W1a, Q = u2e@W1b + b1 ----------------
// Output-chunked (16 cols at a time) to keep accumulator at 8 ull (16 regs).
__global__ __launch_bounds__(256) void prep_kernel(const float* __restrict__ u2e,
                                                   const float* __restrict__ W1,
                                                   const float* __restrict__ b1,
                                                   int V) {
    __shared__ ulonglong2 sW1[128 * 16];   // 32KB: W1 [128,64] as f32x2 pairs
    __shared__ float sb1[64];
    {
        const float4* W1v = (const float4*)W1;
        float4* sv = (float4*)sW1;
        for (int i = threadIdx.x; i < 128 * 16; i += 256) sv[i] = W1v[i];
        if (threadIdx.x < 64) sb1[threadIdx.x] = b1[threadIdx.x];
    }
    __syncthreads();

    int v = blockIdx.x * blockDim.x + threadIdx.x;
    if (v >= V) return;

    float r[D];
    const float4* row = (const float4*)(u2e + (size_t)v * D);
#pragma unroll
    for (int i = 0; i < 16; i++) {
        float4 t = row[i];
        r[4 * i + 0] = t.x; r[4 * i + 1] = t.y; r[4 * i + 2] = t.z; r[4 * i + 3] = t.w;
    }

    float4* Pr = (float4*)(g_P + (size_t)v * D);
    float4* Qr = (float4*)(g_Q + (size_t)v * D);

    // ---- P = r @ W1a, chunk of 16 outputs at a time ----
#pragma unroll
    for (int c = 0; c < 4; c++) {
        unsigned long long acc[8];
#pragma unroll
        for (int j = 0; j < 8; j++) acc[j] = 0ull;
#pragma unroll
        for (int i = 0; i < 64; i++) {
            unsigned long long a2 = pack2(r[i], r[i]);
            const ulonglong2* wr = sW1 + i * 16 + c * 4;
#pragma unroll
            for (int jj = 0; jj < 4; jj++) {
                ulonglong2 w = wr[jj];
                acc[2 * jj]     = fma2(a2, w.x, acc[2 * jj]);
                acc[2 * jj + 1] = fma2(a2, w.y, acc[2 * jj + 1]);
            }
        }
#pragma unroll
        for (int jj = 0; jj < 4; jj++) {
            float a, b, cc, d2;
            unpack2(acc[2 * jj], a, b);
            unpack2(acc[2 * jj + 1], cc, d2);
            Pr[c * 4 + jj] = make_float4(a, b, cc, d2);
        }
    }

    // ---- Q = r @ W1b + b1 ----
#pragma unroll
    for (int c = 0; c < 4; c++) {
        unsigned long long acc[8];
#pragma unroll
        for (int j = 0; j < 8; j++)
            acc[j] = pack2(sb1[c * 16 + 2 * j], sb1[c * 16 + 2 * j + 1]);
#pragma unroll
        for (int i = 0; i < 64; i++) {
            unsigned long long a2 = pack2(r[i], r[i]);
            const ulonglong2* wr = sW1 + (64 + i) * 16 + c * 4;
#pragma unroll
            for (int jj = 0; jj < 4; jj++) {
                ulonglong2 w = wr[jj];
                acc[2 * jj]     = fma2(a2, w.x, acc[2 * jj]);
                acc[2 * jj + 1] = fma2(a2, w.y, acc[2 * jj + 1]);
            }
        }
#pragma unroll
        for (int jj = 0; jj < 4; jj++) {
            float a, b, cc, d2;
            unpack2(acc[2 * jj], a, b);
            unpack2(acc[2 * jj + 1], cc, d2);
            Qr[c * 4 + jj] = make_float4(a, b, cc, d2);
        }
    }
}

// ---------------- reduce-scatter stage (warp-wide column sums) ----------------
template <int OFF, int HALF>
__device__ __forceinline__ void rs_stage(float* part, int lane) {
    bool up = (lane & OFF) != 0;
#pragma unroll
    for (int j = 0; j < HALF; j++) {
        float send  = up ? part[j] : part[j + HALF];
        float other = __shfl_xor_sync(0xffffffffu, send, OFF);
        float keep  = up ? part[j + HALF] : part[j];
        part[j] = keep + other;
    }
}

// ---------------- main fused kernel: one warp per node, one lane per neighbor ----------------
__global__ __launch_bounds__(128, 3) void agg_kernel(
    const float* __restrict__ u2e,
    const float* __restrict__ W2, const float* __restrict__ b2,
    const float* __restrict__ W3, const float* __restrict__ b3,
    const int* __restrict__ nodes, const int* __restrict__ neigh_idx,
    float* __restrict__ out, int n_nodes) {
    __shared__ ulonglong2 sW2[64 * 16];   // 16KB: W2 [64,64] as f32x2 pairs
    __shared__ float sW3[64];
    __shared__ float sb2[64];
    {
        const float4* W2v = (const float4*)W2;
        float4* sv = (float4*)sW2;
        for (int i = threadIdx.x; i < 1024; i += 128) sv[i] = W2v[i];
        if (threadIdx.x < 64) { sW3[threadIdx.x] = W3[threadIdx.x]; sb2[threadIdx.x] = b2[threadIdx.x]; }
    }
    __syncthreads();

    int warp = threadIdx.x >> 5, lane = threadIdx.x & 31;
    int n = blockIdx.x * 4 + warp;
    if (n >= n_nodes) return;

    int node = nodes[n];                       // uniform per warp
    int idx  = neigh_idx[n * K + lane];        // this lane's neighbor
    unsigned int m = (g_mask[n] >> lane) & 1u;

    // ---- layer 1: h1 = relu(P[idx] + Q[node])  (Q already contains b1) ----
    float h1[D];
    {
        const float4* Pr = (const float4*)(g_P + (size_t)idx * D);
        const float4* Qr = (const float4*)(g_Q + (size_t)node * D);
#pragma unroll
        for (int i = 0; i < 16; i++) {
            float4 p = Pr[i];
            float4 q = Qr[i];
            h1[4 * i + 0] = fmaxf(p.x + q.x, 0.f);
            h1[4 * i + 1] = fmaxf(p.y + q.y, 0.f);
            h1[4 * i + 2] = fmaxf(p.z + q.z, 0.f);
            h1[4 * i + 3] = fmaxf(p.w + q.w, 0.f);
        }
    }

    // ---- layers 2+3 fused, output-chunked: 16 h2 cols at a time ----
    // score = b3 + sum_j relu(h2_j) * W3_j, h2 = h1 @ W2 + b2
    float score = b3[0];
#pragma unroll
    for (int c = 0; c < 4; c++) {
        unsigned long long acc[8];
#pragma unroll
        for (int j = 0; j < 8; j++)
            acc[j] = pack2(sb2[c * 16 + 2 * j], sb2[c * 16 + 2 * j + 1]);
#pragma unroll
        for (int i = 0; i < 64; i++) {
            unsigned long long a2 = pack2(h1[i], h1[i]);
            const ulonglong2* wr = sW2 + i * 16 + c * 4;
#pragma unroll
            for (int jj = 0; jj < 4; jj++) {
                ulonglong2 w = wr[jj];
                acc[2 * jj]     = fma2(a2, w.x, acc[2 * jj]);
                acc[2 * jj + 1] = fma2(a2, w.y, acc[2 * jj + 1]);
            }
        }
#pragma unroll
        for (int j = 0; j < 8; j++) {
            float lo, hi;
            unpack2(acc[j], lo, hi);
            score = fmaf(fmaxf(lo, 0.f), sW3[c * 16 + 2 * j], score);
            score = fmaf(fmaxf(hi, 0.f), sW3[c * 16 + 2 * j + 1], score);
        }
    }

    // ---- masked softmax across the warp (K = 32 = warp width) ----
    float s = m ? score : -1e30f;
    float mx = s;
#pragma unroll
    for (int o = 16; o; o >>= 1) mx = fmaxf(mx, __shfl_xor_sync(0xffffffffu, mx, o));
    float e = __expf(s - mx);                  // masked lanes underflow to exactly 0
    float sum = e;
#pragma unroll
    for (int o = 16; o; o >>= 1) sum += __shfl_xor_sync(0xffffffffu, sum, o);
    float att = __fdividef(e, sum);

    // ---- out[n] = sum_k att_k * u2e[idx_k] : reduce-scatter over the warp ----
    float part[D];
    {
        const float4* Er = (const float4*)(u2e + (size_t)idx * D);
#pragma unroll
        for (int i = 0; i < 16; i++) {
            float4 v = Er[i];
            part[4 * i + 0] = v.x * att;
            part[4 * i + 1] = v.y * att;
            part[4 * i + 2] = v.z * att;
            part[4 * i + 3] = v.w * att;
        }
    }
    rs_stage<16, 32>(part, lane);
    rs_stage<8, 16>(part, lane);
    rs_stage<4, 8>(part, lane);
    rs_stage<2, 4>(part, lane);
    rs_stage<1, 2>(part, lane);
    ((float2*)out)[n * 32 + lane] = make_float2(part[0], part[1]);
}

// ---------------- launch ----------------
// Input order (metadata): u2e, W1, b1, W2, b2, W3, b3, nodes, neigh_idx, neigh_mask
extern "C" void kernel_launch(void* const* d_in, const int* in_sizes, int n_in,
                              void* d_out, int out_size) {
    const float* u2e = (const float*)d_in[0];
    const float* W1  = (const float*)d_in[1];
    const float* b1  = (const float*)d_in[2];
    const float* W2  = (const float*)d_in[3];
    const float* b2  = (const float*)d_in[4];
    const float* W3  = (const float*)d_in[5];
    const float* b3  = (const float*)d_in[6];
    const int*   nodes     = (const int*)d_in[7];
    const int*   neigh_idx = (const int*)d_in[8];
    const void*  neigh_mask = d_in[9];
    float* out = (float*)d_out;

    int V = in_sizes[0] / D;
    if (V > VOCAB_MAX) V = VOCAB_MAX;
    int n_nodes = in_sizes[7];
    int mask_elems = in_sizes[9];
    int n_words = mask_elems / 4;

    mask_init_kernel<<<1, 1>>>();
    mask_detect_kernel<<<256, 256>>>((const unsigned int*)neigh_mask, n_words);
    mask_convert_kernel<<<(n_nodes + 255) / 256, 256>>>(neigh_mask, n_nodes);
    prep_kernel<<<(V + 255) / 256, 256>>>(u2e, W1, b1, V);
    agg_kernel<<<(n_nodes + 3) / 4, 128>>>(u2e, W2, b2, W3, b3,
                                           nodes, neigh_idx, out, n_nodes);
}